// round 13
// baseline (speedup 1.0000x reference)
#include <cuda_runtime.h>
#include <cstdint>

// ---------------- problem constants ----------------
#define USERN 100000
#define ITEMN 50000
#define TAGN  20000
#define NN (USERN + ITEMN)   // 150000 interaction-graph nodes
#define MM (ITEMN + TAGN)    // 70000 tag-graph nodes
#define DD 64
#define Q4 16                // float4 per embedding row
#define Q2 32                // float2 per embedding row
#define E_ADJ 2000000
#define E_TAG 1000000
#define E_SOC 1000000

// ---------------- device scratch (no allocs allowed) ----------------
__device__ float g_lat[NN * DD];
__device__ float g_taglat[MM * DD];
__device__ float g_tem[NN * DD];     // adj-graph row sums (gather output)
__device__ float g_tg[MM * DD];      // tag-graph row sums
__device__ float g_soc[USERN * DD];  // social-graph row sums
__device__ float g_wadj[E_ADJ];
__device__ float g_wtag[E_TAG];
__device__ float g_wsoc[E_SOC];

// CSR scratch (structure is identical across layers; built once per call)
__device__ int g_cnt_adj[NN];
__device__ int g_off_adj[NN + 1];
__device__ int g_cur_adj[NN];
__device__ int g_cnt_tag[MM];
__device__ int g_off_tag[MM + 1];
__device__ int g_cur_tag[MM];
__device__ int g_cnt_soc[USERN];
__device__ int g_off_soc[USERN + 1];
__device__ int g_cur_soc[USERN];
__device__ int2 g_ce_adj[E_ADJ];     // (col, edge-id) binned by row
__device__ int2 g_ce_tag[E_TAG];
__device__ int2 g_ce_soc[E_SOC];

// ---------------- threefry-2x32 (exact JAX implementation) ----------------
__host__ __device__ __forceinline__ void tf2x32(uint32_t k0, uint32_t k1,
                                                uint32_t x0, uint32_t x1,
                                                uint32_t& o0, uint32_t& o1) {
    uint32_t ks2 = k0 ^ k1 ^ 0x1BD11BDAu;
    x0 += k0; x1 += k1;
#define TF_RR(r) { x0 += x1; x1 = (x1 << (r)) | (x1 >> (32 - (r))); x1 ^= x0; }
    TF_RR(13) TF_RR(15) TF_RR(26) TF_RR(6)   x0 += k1;  x1 += ks2 + 1u;
    TF_RR(17) TF_RR(29) TF_RR(16) TF_RR(24)  x0 += ks2; x1 += k0 + 2u;
    TF_RR(13) TF_RR(15) TF_RR(26) TF_RR(6)   x0 += k0;  x1 += k1 + 3u;
    TF_RR(17) TF_RR(29) TF_RR(16) TF_RR(24)  x0 += k1;  x1 += ks2 + 4u;
    TF_RR(13) TF_RR(15) TF_RR(26) TF_RR(6)   x0 += ks2; x1 += k0 + 5u;
#undef TF_RR
    o0 = x0; o1 = x1;
}

// ---------------- init: embeddings + acc seed (no zeroing needed) ----------
__global__ void init_kernel(const float4* __restrict__ uE,
                            const float4* __restrict__ iE,
                            const float4* __restrict__ tE,
                            float4* __restrict__ out) {
    int t = blockIdx.x * blockDim.x + threadIdx.x;
    if (t < NN * Q4) {
        float4 v = (t < USERN * Q4) ? uE[t] : iE[t - USERN * Q4];
        reinterpret_cast<float4*>(g_lat)[t] = v;
        out[t] = v;                                    // acc starts at lat
    }
    if (t < MM * Q4) {
        float4 v = (t < ITEMN * Q4) ? iE[t] : tE[t - ITEMN * Q4];
        reinterpret_cast<float4*>(g_taglat)[t] = v;
    }
}

// ---------------- CSR build (once per call) -------------------------------
__global__ void zero_cnt_kernel() {
    int t = blockIdx.x * blockDim.x + threadIdx.x;
    if (t < NN) g_cnt_adj[t] = 0;
    if (t < MM) g_cnt_tag[t] = 0;
    if (t < USERN) g_cnt_soc[t] = 0;
}

template <int G>
__global__ void hist_kernel(const int* __restrict__ rows, int E) {
    int e = blockIdx.x * blockDim.x + threadIdx.x;
    if (e >= E) return;
    int* cnt = (G == 0) ? g_cnt_adj : (G == 1) ? g_cnt_tag : g_cnt_soc;
    atomicAdd(cnt + rows[e], 1);
}

// Single-block exclusive scan: thread t owns a contiguous chunk; sequential
// chunk sums -> shared Hillis-Steele over 1024 partials -> sequential write.
template <int G>
__global__ void scan_kernel(int n) {
    __shared__ int ssum[1024];
    const int* cnt = (G == 0) ? g_cnt_adj : (G == 1) ? g_cnt_tag : g_cnt_soc;
    int* off = (G == 0) ? g_off_adj : (G == 1) ? g_off_tag : g_off_soc;
    int* cur = (G == 0) ? g_cur_adj : (G == 1) ? g_cur_tag : g_cur_soc;
    int t = threadIdx.x;
    int chunk = (n + 1023) >> 10;
    int beg = t * chunk;
    int end = min(beg + chunk, n);
    int s = 0;
    for (int i = beg; i < end; ++i) s += cnt[i];
    ssum[t] = s;
    __syncthreads();
    for (int d = 1; d < 1024; d <<= 1) {
        int v = 0;
        if (t >= d) v = ssum[t - d];
        __syncthreads();
        if (t >= d) ssum[t] += v;
        __syncthreads();
    }
    int run = (t == 0) ? 0 : ssum[t - 1];
    for (int i = beg; i < end; ++i) {
        off[i] = run;
        cur[i] = run;
        run += cnt[i];
    }
    if (t == 1023) off[n] = ssum[1023];
}

template <int G>
__global__ void bin_kernel(const int* __restrict__ rows,
                           const int* __restrict__ cols, int E) {
    int e = blockIdx.x * blockDim.x + threadIdx.x;
    if (e >= E) return;
    int* cur = (G == 0) ? g_cur_adj : (G == 1) ? g_cur_tag : g_cur_soc;
    int2* ce = (G == 0) ? g_ce_adj : (G == 1) ? g_ce_tag : g_ce_soc;
    int r = rows[e];
    int pos = atomicAdd(cur + r, 1);
    ce[pos] = make_int2(cols[e], e);
}

// ---------------- per-layer dropout weights (bit-exact JAX threefry) -------
// jax_threefry_partitionable=True: bits(e) = fold_xor(threefry2x32(key, 0, e))
template <int W>
__global__ void weights_kernel(const float* __restrict__ vals, int E,
                               uint32_t k0, uint32_t k1) {
    int e = blockIdx.x * blockDim.x + threadIdx.x;
    if (e >= E) return;
    float* w = (W == 0) ? g_wadj : (W == 1) ? g_wtag : g_wsoc;
    uint32_t o0, o1;
    tf2x32(k0, k1, 0u, (uint32_t)e, o0, o1);
    uint32_t bits = o0 ^ o1;
    const float INVKEEP = (float)(1.0 / 0.9);
    float u = __uint_as_float((bits >> 9) | 0x3f800000u) - 1.0f;
    float m = floorf(u + 0.9f);   // 0 or 1, bit-exact vs jnp.floor(u + KEEP)
    w[e] = vals[e] * m * INVKEEP;
}

// ---------------- gather: one warp per destination row ---------------------
// 32 lanes x float2 = 64 floats. Per edge: one uniform int2 (binned, ~sequential),
// one random 4B weight, one 256B coalesced source-row read. One plain 256B
// store per row at the end — no atomics anywhere.
// MODE 0: adj (src g_lat,   dst g_tem,  R=NN)
// MODE 1: tag (src lat[USER+c] if c<ITEM else taglat[c], dst g_tg, R=MM)
// MODE 2: soc (src g_lat,   dst g_soc, R=USERN)
template <int MODE>
__global__ void gather_kernel(int R) {
    int warp = (blockIdx.x * blockDim.x + threadIdx.x) >> 5;
    int lane = threadIdx.x & 31;
    if (warp >= R) return;
    const int* off = (MODE == 0) ? g_off_adj : (MODE == 1) ? g_off_tag : g_off_soc;
    const int2* ce = (MODE == 0) ? g_ce_adj : (MODE == 1) ? g_ce_tag : g_ce_soc;
    const float* w = (MODE == 0) ? g_wadj : (MODE == 1) ? g_wtag : g_wsoc;
    float* dst = (MODE == 0) ? g_tem : (MODE == 1) ? g_tg : g_soc;
    const float2* lat2 = reinterpret_cast<const float2*>(g_lat);
    const float2* tl2  = reinterpret_cast<const float2*>(g_taglat);

    int beg = off[warp];
    int end = off[warp + 1];
    float2 acc = make_float2(0.f, 0.f);
    for (int i = beg; i < end; ++i) {
        int2 c = __ldg(ce + i);
        float we = __ldg(w + c.y);
        if (we != 0.f) {
            const float2* s;
            if (MODE == 1) {
                s = (c.x < ITEMN) ? lat2 + (size_t)(USERN + c.x) * Q2
                                  : tl2 + (size_t)c.x * Q2;
            } else {
                s = lat2 + (size_t)c.x * Q2;
            }
            float2 v = s[lane];
            acc.x += we * v.x;
            acc.y += we * v.y;
        }
    }
    reinterpret_cast<float2*>(dst)[(size_t)warp * Q2 + lane] = acc;
}

// ---------------- combine ---------------------------------------------------
__device__ __forceinline__ float lk(float x) { return x >= 0.f ? x : 0.5f * x; }
__device__ __forceinline__ float4 lk4(float4 h) {
    return make_float4(lk(h.x), lk(h.y), lk(h.z), lk(h.w));
}

// LeakyReLU + merge + acc update. All row-sum buffers are plain-overwritten by
// the next layer's gathers, so nothing is zeroed here.
__global__ void combine_kernel(float4* __restrict__ out) {
    int t = blockIdx.x * blockDim.x + threadIdx.x;
    if (t < NN * Q4) {
        float4 h = reinterpret_cast<float4*>(g_tem)[t];
        float4 o = lk4(h);
        if (t < USERN * Q4) {
            float4 s = lk4(reinterpret_cast<float4*>(g_soc)[t]);
            o.x += s.x; o.y += s.y; o.z += s.z; o.w += s.w;
        } else {
            float4 g = lk4(reinterpret_cast<float4*>(g_tg)[t - USERN * Q4]);
            o.x += g.x; o.y += g.y; o.z += g.z; o.w += g.w;
        }
        reinterpret_cast<float4*>(g_lat)[t] = o;
        float4 a = out[t];
        out[t] = make_float4(a.x + o.x, a.y + o.y, a.z + o.z, a.w + o.w);
    }
    if (t < MM * Q4) {
        reinterpret_cast<float4*>(g_taglat)[t] =
            lk4(reinterpret_cast<float4*>(g_tg)[t]);
    }
}

// ---------------- launch ----------------------------------------------------
extern "C" void kernel_launch(void* const* d_in, const int* in_sizes, int n_in,
                              void* d_out, int out_size) {
    const float4* uE   = (const float4*)d_in[0];
    const float4* iE   = (const float4*)d_in[1];
    const float4* tE   = (const float4*)d_in[2];
    const int*   adj_r = (const int*)d_in[3];
    const int*   adj_c = (const int*)d_in[4];
    const float* adj_v = (const float*)d_in[5];
    const int*   tag_r = (const int*)d_in[6];
    const int*   tag_c = (const int*)d_in[7];
    const float* tag_v = (const float*)d_in[8];
    const int*   soc_r = (const int*)d_in[9];
    const int*   soc_c = (const int*)d_in[10];
    const float* soc_v = (const float*)d_in[11];
    float4* out = (float4*)d_out;

    const int T = 256;
    auto cdiv = [](long long a, long long b) { return (int)((a + b - 1) / b); };

    init_kernel<<<cdiv((long long)NN * Q4, T), T>>>(uE, iE, tE, out);

    // --- CSR build (structure shared by both layers) ---
    zero_cnt_kernel<<<cdiv(NN, T), T>>>();
    hist_kernel<0><<<cdiv(E_ADJ, T), T>>>(adj_r, E_ADJ);
    hist_kernel<1><<<cdiv(E_TAG, T), T>>>(tag_r, E_TAG);
    hist_kernel<2><<<cdiv(E_SOC, T), T>>>(soc_r, E_SOC);
    scan_kernel<0><<<1, 1024>>>(NN);
    scan_kernel<1><<<1, 1024>>>(MM);
    scan_kernel<2><<<1, 1024>>>(USERN);
    bin_kernel<0><<<cdiv(E_ADJ, T), T>>>(adj_r, adj_c, E_ADJ);
    bin_kernel<1><<<cdiv(E_TAG, T), T>>>(tag_r, tag_c, E_TAG);
    bin_kernel<2><<<cdiv(E_SOC, T), T>>>(soc_r, soc_c, E_SOC);

    // Fold dropout keys on the host: key(42) = (0, 42); fold_in(key, d) =
    // threefry_2x32(key, (0, d)). fold_in is NOT affected by the
    // threefry_partitionable flag — only random_bits is.
    uint32_t kk[6][2];
    for (int d = 0; d < 6; ++d)
        tf2x32(0u, 42u, 0u, (uint32_t)d, kk[d][0], kk[d][1]);

    for (int L = 0; L < 2; ++L) {
        weights_kernel<0><<<cdiv(E_ADJ, T), T>>>(adj_v, E_ADJ,
                                                 kk[3 * L][0], kk[3 * L][1]);
        weights_kernel<1><<<cdiv(E_TAG, T), T>>>(tag_v, E_TAG,
                                                 kk[3 * L + 1][0], kk[3 * L + 1][1]);
        weights_kernel<2><<<cdiv(E_SOC, T), T>>>(soc_v, E_SOC,
                                                 kk[3 * L + 2][0], kk[3 * L + 2][1]);
        gather_kernel<0><<<cdiv((long long)NN * 32, T), T>>>(NN);
        gather_kernel<1><<<cdiv((long long)MM * 32, T), T>>>(MM);
        gather_kernel<2><<<cdiv((long long)USERN * 32, T), T>>>(USERN);
        combine_kernel<<<cdiv((long long)NN * Q4, T), T>>>(out);
    }
}

// round 14
// speedup vs baseline: 2.0732x; 2.0732x over previous
#include <cuda_runtime.h>
#include <cstdint>

// ---------------- problem constants ----------------
#define USERN 100000
#define ITEMN 50000
#define TAGN  20000
#define NN (USERN + ITEMN)   // 150000 interaction-graph nodes
#define MM (ITEMN + TAGN)    // 70000 tag-graph nodes
#define DD 64
#define Q4 16                // float4 per embedding row
#define Q2 32                // float2 per embedding row
#define E_ADJ 2000000
#define E_TAG 1000000
#define E_SOC 1000000
#define E_TOT (E_ADJ + E_TAG + E_SOC)

// ---------------- device scratch (no allocs allowed) ----------------
__device__ float g_lat[NN * DD];
__device__ float g_taglat[MM * DD];
__device__ float g_tem[NN * DD];     // adj-graph row sums (gather output)
__device__ float g_tg[MM * DD];      // tag-graph row sums
__device__ float g_soc[USERN * DD];  // social-graph row sums

// CSR scratch (structure constant across layers; built once per call)
__device__ int g_cnt_adj[NN];
__device__ int g_off_adj[NN + 1];
__device__ int g_cur_adj[NN];
__device__ int g_cnt_tag[MM];
__device__ int g_off_tag[MM + 1];
__device__ int g_cur_tag[MM];
__device__ int g_cnt_soc[USERN];
__device__ int g_off_soc[USERN + 1];
__device__ int g_cur_soc[USERN];
__device__ int g_part[3][1024];      // block partials for the 3 scans
// Binned edge records: x=col, y=edge-id, z=val bits, w=pad. 16B aligned.
__device__ int4 g_ce_adj[E_ADJ];
__device__ int4 g_ce_tag[E_TAG];
__device__ int4 g_ce_soc[E_SOC];

// ---------------- threefry-2x32 (exact JAX implementation) ----------------
__host__ __device__ __forceinline__ void tf2x32(uint32_t k0, uint32_t k1,
                                                uint32_t x0, uint32_t x1,
                                                uint32_t& o0, uint32_t& o1) {
    uint32_t ks2 = k0 ^ k1 ^ 0x1BD11BDAu;
    x0 += k0; x1 += k1;
#define TF_RR(r) { x0 += x1; x1 = (x1 << (r)) | (x1 >> (32 - (r))); x1 ^= x0; }
    TF_RR(13) TF_RR(15) TF_RR(26) TF_RR(6)   x0 += k1;  x1 += ks2 + 1u;
    TF_RR(17) TF_RR(29) TF_RR(16) TF_RR(24)  x0 += ks2; x1 += k0 + 2u;
    TF_RR(13) TF_RR(15) TF_RR(26) TF_RR(6)   x0 += k0;  x1 += k1 + 3u;
    TF_RR(17) TF_RR(29) TF_RR(16) TF_RR(24)  x0 += k1;  x1 += ks2 + 4u;
    TF_RR(13) TF_RR(15) TF_RR(26) TF_RR(6)   x0 += ks2; x1 += k0 + 5u;
#undef TF_RR
    o0 = x0; o1 = x1;
}

// ---------------- init: embeddings + acc seed ------------------------------
__global__ void init_kernel(const float4* __restrict__ uE,
                            const float4* __restrict__ iE,
                            const float4* __restrict__ tE,
                            float4* __restrict__ out) {
    int t = blockIdx.x * blockDim.x + threadIdx.x;
    if (t < NN * Q4) {
        float4 v = (t < USERN * Q4) ? uE[t] : iE[t - USERN * Q4];
        reinterpret_cast<float4*>(g_lat)[t] = v;
        out[t] = v;                                    // acc starts at lat
    }
    if (t < MM * Q4) {
        float4 v = (t < ITEMN * Q4) ? iE[t] : tE[t - ITEMN * Q4];
        reinterpret_cast<float4*>(g_taglat)[t] = v;
    }
}

// ---------------- CSR build (once per call) --------------------------------
__global__ void zero_cnt_kernel() {
    int t = blockIdx.x * blockDim.x + threadIdx.x;
    if (t < NN) g_cnt_adj[t] = 0;
    if (t < MM) g_cnt_tag[t] = 0;
    if (t < USERN) g_cnt_soc[t] = 0;
}

// One launch histograms all three graphs (4M spread atomics).
__global__ void hist_all_kernel(const int* __restrict__ ar,
                                const int* __restrict__ tr,
                                const int* __restrict__ sr) {
    int t = blockIdx.x * blockDim.x + threadIdx.x;
    if (t < E_ADJ)            atomicAdd(g_cnt_adj + ar[t], 1);
    else if (t < E_ADJ + E_TAG) atomicAdd(g_cnt_tag + tr[t - E_ADJ], 1);
    else if (t < E_TOT)       atomicAdd(g_cnt_soc + sr[t - E_ADJ - E_TAG], 1);
}

// --- 3-pass parallel exclusive scan (n <= 256*1024) ---
template <int G>
__global__ void scanA_kernel(int n) {           // block partial sums
    __shared__ int s[256];
    const int* cnt = (G == 0) ? g_cnt_adj : (G == 1) ? g_cnt_tag : g_cnt_soc;
    int t = threadIdx.x;
    int i = blockIdx.x * 256 + t;
    s[t] = (i < n) ? cnt[i] : 0;
    __syncthreads();
    for (int d = 128; d > 0; d >>= 1) {
        if (t < d) s[t] += s[t + d];
        __syncthreads();
    }
    if (t == 0) g_part[G][blockIdx.x] = s[0];
}

template <int G>
__global__ void scanB_kernel(int nb) {          // scan the <=1024 partials
    __shared__ int s[1024];
    int t = threadIdx.x;
    s[t] = (t < nb) ? g_part[G][t] : 0;
    __syncthreads();
    for (int d = 1; d < 1024; d <<= 1) {
        int v = 0;
        if (t >= d) v = s[t - d];
        __syncthreads();
        if (t >= d) s[t] += v;
        __syncthreads();
    }
    if (t < nb) g_part[G][t] = (t == 0) ? 0 : s[t - 1];  // exclusive
}

template <int G>
__global__ void scanC_kernel(int n) {           // final offsets
    __shared__ int s[256];
    const int* cnt = (G == 0) ? g_cnt_adj : (G == 1) ? g_cnt_tag : g_cnt_soc;
    int* off = (G == 0) ? g_off_adj : (G == 1) ? g_off_tag : g_off_soc;
    int* cur = (G == 0) ? g_cur_adj : (G == 1) ? g_cur_tag : g_cur_soc;
    int t = threadIdx.x;
    int i = blockIdx.x * 256 + t;
    int c = (i < n) ? cnt[i] : 0;
    s[t] = c;
    __syncthreads();
    for (int d = 1; d < 256; d <<= 1) {
        int v = 0;
        if (t >= d) v = s[t - d];
        __syncthreads();
        if (t >= d) s[t] += v;
        __syncthreads();
    }
    if (i < n) {
        int excl = g_part[G][blockIdx.x] + s[t] - c;
        off[i] = excl;
        cur[i] = excl;
        if (i == n - 1) off[n] = excl + c;
    }
}

// One launch bins all three graphs: record = (col, e, val bits, 0).
__global__ void bin_all_kernel(const int* __restrict__ ar, const int* __restrict__ ac,
                               const float* __restrict__ av,
                               const int* __restrict__ tr, const int* __restrict__ tc,
                               const float* __restrict__ tv,
                               const int* __restrict__ sr, const int* __restrict__ sc,
                               const float* __restrict__ sv) {
    int t = blockIdx.x * blockDim.x + threadIdx.x;
    if (t < E_ADJ) {
        int pos = atomicAdd(g_cur_adj + ar[t], 1);
        g_ce_adj[pos] = make_int4(ac[t], t, __float_as_int(av[t]), 0);
    } else if (t < E_ADJ + E_TAG) {
        int e = t - E_ADJ;
        int pos = atomicAdd(g_cur_tag + tr[e], 1);
        g_ce_tag[pos] = make_int4(tc[e], e, __float_as_int(tv[e]), 0);
    } else if (t < E_TOT) {
        int e = t - E_ADJ - E_TAG;
        int pos = atomicAdd(g_cur_soc + sr[e], 1);
        g_ce_soc[pos] = make_int4(sc[e], e, __float_as_int(sv[e]), 0);
    }
}

// ---------------- gather: one warp per destination row ---------------------
// Processes edges in chunks of 32: lane loads its own (col,e,val) record,
// computes the bit-exact JAX dropout weight in-register (partitionable
// threefry: bits = xor-fold of threefry2x32(key, 0, e)), then 32 broadcast
// iterations each doing one independent coalesced 256B row read + FMA.
// No per-layer weight arrays, no random weight loads, no atomics.
template <int MODE>
__global__ void gather_kernel(int R, uint32_t k0, uint32_t k1) {
    int warp = (blockIdx.x * blockDim.x + threadIdx.x) >> 5;
    int lane = threadIdx.x & 31;
    if (warp >= R) return;
    const int* off = (MODE == 0) ? g_off_adj : (MODE == 1) ? g_off_tag : g_off_soc;
    const int4* ce = (MODE == 0) ? g_ce_adj : (MODE == 1) ? g_ce_tag : g_ce_soc;
    float* dst = (MODE == 0) ? g_tem : (MODE == 1) ? g_tg : g_soc;
    const float2* lat2 = reinterpret_cast<const float2*>(g_lat);
    const float2* tl2  = reinterpret_cast<const float2*>(g_taglat);
    const float INVKEEP = (float)(1.0 / 0.9);

    int beg = off[warp];
    int end = off[warp + 1];
    float2 acc = make_float2(0.f, 0.f);
    for (int base = beg; base < end; base += 32) {
        int m = end - base; if (m > 32) m = 32;
        int col = 0;
        float wgt = 0.f;
        if (lane < m) {
            int4 c = __ldg(ce + base + lane);
            col = c.x;
            uint32_t o0, o1;
            tf2x32(k0, k1, 0u, (uint32_t)c.y, o0, o1);
            uint32_t bits = o0 ^ o1;
            float u = __uint_as_float((bits >> 9) | 0x3f800000u) - 1.0f;
            float msk = floorf(u + 0.9f);           // 0 or 1, bit-exact
            wgt = __int_as_float(c.z) * msk * INVKEEP;
        }
        #pragma unroll 4
        for (int j = 0; j < m; ++j) {
            float we = __shfl_sync(0xffffffffu, wgt, j);
            int cc = __shfl_sync(0xffffffffu, col, j);
            if (we != 0.f) {
                const float2* s;
                if (MODE == 1) {
                    s = (cc < ITEMN) ? lat2 + (size_t)(USERN + cc) * Q2
                                     : tl2 + (size_t)cc * Q2;
                } else {
                    s = lat2 + (size_t)cc * Q2;
                }
                float2 v = s[lane];
                acc.x += we * v.x;
                acc.y += we * v.y;
            }
        }
    }
    reinterpret_cast<float2*>(dst)[(size_t)warp * Q2 + lane] = acc;
}

// ---------------- combine ---------------------------------------------------
__device__ __forceinline__ float lk(float x) { return x >= 0.f ? x : 0.5f * x; }
__device__ __forceinline__ float4 lk4(float4 h) {
    return make_float4(lk(h.x), lk(h.y), lk(h.z), lk(h.w));
}

// LeakyReLU + merge + acc update. Row-sum buffers are plain-overwritten by the
// next layer's gathers, so nothing is zeroed.
__global__ void combine_kernel(float4* __restrict__ out) {
    int t = blockIdx.x * blockDim.x + threadIdx.x;
    if (t < NN * Q4) {
        float4 h = reinterpret_cast<float4*>(g_tem)[t];
        float4 o = lk4(h);
        if (t < USERN * Q4) {
            float4 s = lk4(reinterpret_cast<float4*>(g_soc)[t]);
            o.x += s.x; o.y += s.y; o.z += s.z; o.w += s.w;
        } else {
            float4 g = lk4(reinterpret_cast<float4*>(g_tg)[t - USERN * Q4]);
            o.x += g.x; o.y += g.y; o.z += g.z; o.w += g.w;
        }
        reinterpret_cast<float4*>(g_lat)[t] = o;
        float4 a = out[t];
        out[t] = make_float4(a.x + o.x, a.y + o.y, a.z + o.z, a.w + o.w);
    }
    if (t < MM * Q4) {
        reinterpret_cast<float4*>(g_taglat)[t] =
            lk4(reinterpret_cast<float4*>(g_tg)[t]);
    }
}

// ---------------- launch ----------------------------------------------------
extern "C" void kernel_launch(void* const* d_in, const int* in_sizes, int n_in,
                              void* d_out, int out_size) {
    const float4* uE   = (const float4*)d_in[0];
    const float4* iE   = (const float4*)d_in[1];
    const float4* tE   = (const float4*)d_in[2];
    const int*   adj_r = (const int*)d_in[3];
    const int*   adj_c = (const int*)d_in[4];
    const float* adj_v = (const float*)d_in[5];
    const int*   tag_r = (const int*)d_in[6];
    const int*   tag_c = (const int*)d_in[7];
    const float* tag_v = (const float*)d_in[8];
    const int*   soc_r = (const int*)d_in[9];
    const int*   soc_c = (const int*)d_in[10];
    const float* soc_v = (const float*)d_in[11];
    float4* out = (float4*)d_out;

    const int T = 256;
    auto cdiv = [](long long a, long long b) { return (int)((a + b - 1) / b); };

    init_kernel<<<cdiv((long long)NN * Q4, T), T>>>(uE, iE, tE, out);

    // --- CSR build (structure shared by both layers) ---
    zero_cnt_kernel<<<cdiv(NN, T), T>>>();
    hist_all_kernel<<<cdiv(E_TOT, T), T>>>(adj_r, tag_r, soc_r);
    scanA_kernel<0><<<cdiv(NN, 256), 256>>>(NN);
    scanA_kernel<1><<<cdiv(MM, 256), 256>>>(MM);
    scanA_kernel<2><<<cdiv(USERN, 256), 256>>>(USERN);
    scanB_kernel<0><<<1, 1024>>>(cdiv(NN, 256));
    scanB_kernel<1><<<1, 1024>>>(cdiv(MM, 256));
    scanB_kernel<2><<<1, 1024>>>(cdiv(USERN, 256));
    scanC_kernel<0><<<cdiv(NN, 256), 256>>>(NN);
    scanC_kernel<1><<<cdiv(MM, 256), 256>>>(MM);
    scanC_kernel<2><<<cdiv(USERN, 256), 256>>>(USERN);
    bin_all_kernel<<<cdiv(E_TOT, T), T>>>(adj_r, adj_c, adj_v,
                                          tag_r, tag_c, tag_v,
                                          soc_r, soc_c, soc_v);

    // Fold dropout keys on the host: key(42) = (0, 42); fold_in(key, d) =
    // threefry_2x32(key, (0, d)). fold_in is NOT affected by the
    // threefry_partitionable flag — only random_bits is.
    uint32_t kk[6][2];
    for (int d = 0; d < 6; ++d)
        tf2x32(0u, 42u, 0u, (uint32_t)d, kk[d][0], kk[d][1]);

    for (int L = 0; L < 2; ++L) {
        gather_kernel<0><<<cdiv((long long)NN * 32, T), T>>>(NN, kk[3 * L][0], kk[3 * L][1]);
        gather_kernel<1><<<cdiv((long long)MM * 32, T), T>>>(MM, kk[3 * L + 1][0], kk[3 * L + 1][1]);
        gather_kernel<2><<<cdiv((long long)USERN * 32, T), T>>>(USERN, kk[3 * L + 2][0], kk[3 * L + 2][1]);
        combine_kernel<<<cdiv((long long)NN * Q4, T), T>>>(out);
    }
}